// round 2
// baseline (speedup 1.0000x reference)
#include <cuda_runtime.h>
#include <math.h>

#define EPSF 1e-5f

// ---------------- scratch (device globals; no allocation allowed) ----------------
__device__ float g_qkv[4194304];      // [128 bh][256 o][128 l]  raw qkv (pre-BN)
__device__ float g_qk[33554432];      // [128 bh][16 g][128 i][128 j]
__device__ float g_outraw[4194304];   // [128 bh][256 o][128 i]  raw am/ame (pre-BN)
__device__ float g_simStats[96];      // [48 ch][sum, sumsq]
__device__ float g_outStats[512];     // [256 ch][sum, sumsq]
__device__ float g_scaleQ[256];
__device__ float g_shiftQ[256];
__device__ float g_simScale[48];
__device__ float g_outScale[256];
__device__ float g_outShift[256];

__device__ __forceinline__ float warpSum(float v) {
#pragma unroll
    for (int o = 16; o > 0; o >>= 1) v += __shfl_xor_sync(0xffffffffu, v, o);
    return v;
}

// ---------------- Z: zero stat accumulators ----------------
__global__ void kZero() {
    int t = threadIdx.x;
    if (t < 96) g_simStats[t] = 0.f;
    g_outStats[t] = 0.f;
    g_outStats[t + 256] = 0.f;
}

// ---------------- A: qkv[bh,o,l] = sum_c W[o,c] * x[b0,c,h,l] ----------------
// grid (ot=2, bh=128), 256 thr, smem: A^T tile (k-major) + X tile, 132-pitch
__global__ __launch_bounds__(256) void kA(const float* __restrict__ x,
                                          const float* __restrict__ W) {
    extern __shared__ float sm[];
    float* sa = sm;              // [128 k][132] : sa[k*132 + o_local]
    float* sb = sm + 16896;      // [128 k][132] : sb[k*132 + l]
    const int ot = blockIdx.x, bh = blockIdx.y;
    const int b0 = bh >> 6, h = bh & 63;
    const int t = threadIdx.x;

    for (int e = 0; e < 64; e++) {
        int idx = e * 256 + t;
        int r = idx >> 7, c = idx & 127;
        sa[c * 132 + r] = W[(ot * 128 + r) * 128 + c];
    }
    for (int e = 0; e < 64; e++) {
        int idx = e * 256 + t;
        int c = idx >> 7, l = idx & 127;
        sb[c * 132 + l] = x[((b0 * 128 + c) * 64 + h) * 128 + l];
    }
    __syncthreads();

    const int ty = t >> 4, tx = t & 15;
    const int i0 = ty * 8, j0 = tx * 8;
    float acc[8][8];
#pragma unroll
    for (int u = 0; u < 8; u++)
#pragma unroll
        for (int v = 0; v < 8; v++) acc[u][v] = 0.f;

#pragma unroll 2
    for (int k = 0; k < 128; k++) {
        float4 A0 = *(const float4*)(sa + k * 132 + i0);
        float4 A1 = *(const float4*)(sa + k * 132 + i0 + 4);
        float4 B0 = *(const float4*)(sb + k * 132 + j0);
        float4 B1 = *(const float4*)(sb + k * 132 + j0 + 4);
        float a[8] = {A0.x, A0.y, A0.z, A0.w, A1.x, A1.y, A1.z, A1.w};
        float b[8] = {B0.x, B0.y, B0.z, B0.w, B1.x, B1.y, B1.z, B1.w};
#pragma unroll
        for (int u = 0; u < 8; u++)
#pragma unroll
            for (int v = 0; v < 8; v++) acc[u][v] += a[u] * b[v];
    }

    float* dst = g_qkv + (size_t)bh * 32768 + (size_t)(ot * 128) * 128;
#pragma unroll
    for (int u = 0; u < 8; u++) {
        *(float4*)(dst + (i0 + u) * 128 + j0)     = make_float4(acc[u][0], acc[u][1], acc[u][2], acc[u][3]);
        *(float4*)(dst + (i0 + u) * 128 + j0 + 4) = make_float4(acc[u][4], acc[u][5], acc[u][6], acc[u][7]);
    }
}

// ---------------- B: per-channel BN stats for qkv (256 ch x 16384) ----------------
__global__ __launch_bounds__(256) void kB(const float* __restrict__ gamma,
                                          const float* __restrict__ beta) {
    const int o = blockIdx.x, t = threadIdx.x;
    float s = 0.f, s2 = 0.f;
    for (int e = 0; e < 64; e++) {
        int n = e * 256 + t;
        float v = g_qkv[(size_t)(n >> 7) * 32768 + o * 128 + (n & 127)];
        s += v; s2 += v * v;
    }
    s = warpSum(s); s2 = warpSum(s2);
    __shared__ float rs[8], rs2[8];
    int w = t >> 5, lane = t & 31;
    if (lane == 0) { rs[w] = s; rs2[w] = s2; }
    __syncthreads();
    if (t == 0) {
        float S = 0.f, S2 = 0.f;
        for (int i = 0; i < 8; i++) { S += rs[i]; S2 += rs2[i]; }
        float mean = S * (1.f / 16384.f);
        float var  = S2 * (1.f / 16384.f) - mean * mean;
        float sc = gamma[o] * rsqrtf(var + EPSF);
        g_scaleQ[o] = sc;
        g_shiftQ[o] = beta[o] - mean * sc;
    }
}

// ---------------- C: per (g,bh): qe/ke in shared, qk = qe^T ke, sim stats ----------------
// grid (g=16, bh=128), 256 thr
__global__ __launch_bounds__(256) void kC(const float* __restrict__ relemb) {
    extern __shared__ float sm[];
    float* sre = sm;             // [8][256]   rel_emb rows 0..7
    float* sq  = sm + 2048;     // [4][128]   (reused as reduction scratch)
    float* sk  = sm + 2560;     // [4][128]
    float* sqe = sm + 3072;     // [128][132]  qe[m][i]
    float* ske = sm + 19968;    // [128][132]  ke[m][j]
    const int g = blockIdx.x, bh = blockIdx.y, t = threadIdx.x;

    for (int n = t; n < 8 * 255; n += 256) {
        int r = n / 255, c = n - r * 255;
        sre[r * 256 + c] = relemb[n];
    }
    for (int n = t; n < 1024; n += 256) {
        int cl = n >> 7, m = n & 127;
        int o = g * 16 + cl;
        float v = g_qkv[(size_t)bh * 32768 + o * 128 + m] * g_scaleQ[o] + g_shiftQ[o];
        if (cl < 4) sq[cl * 128 + m] = v; else sk[(cl - 4) * 128 + m] = v;
    }
    __syncthreads();

    float sQE = 0.f, sQE2 = 0.f, sKE = 0.f, sKE2 = 0.f;
    for (int e = 0; e < 64; e++) {
        int idx = e * 256 + t;
        int m = idx >> 7, i = idx & 127;
        int d = m - i + 127;
        float qe = sq[m] * sre[d] + sq[128 + m] * sre[256 + d] +
                   sq[256 + m] * sre[512 + d] + sq[384 + m] * sre[768 + d];
        float ke = sk[m] * sre[1024 + d] + sk[128 + m] * sre[1280 + d] +
                   sk[256 + m] * sre[1536 + d] + sk[384 + m] * sre[1792 + d];
        sqe[m * 132 + i] = qe;
        ske[m * 132 + i] = ke;
        sQE += qe; sQE2 += qe * qe; sKE += ke; sKE2 += ke * ke;
    }
    __syncthreads();

    const int ty = t >> 4, tx = t & 15;
    const int i0 = ty * 8, j0 = tx * 8;
    float acc[8][8];
#pragma unroll
    for (int u = 0; u < 8; u++)
#pragma unroll
        for (int v = 0; v < 8; v++) acc[u][v] = 0.f;

#pragma unroll 2
    for (int m = 0; m < 128; m++) {
        float4 A0 = *(const float4*)(sqe + m * 132 + i0);
        float4 A1 = *(const float4*)(sqe + m * 132 + i0 + 4);
        float4 B0 = *(const float4*)(ske + m * 132 + j0);
        float4 B1 = *(const float4*)(ske + m * 132 + j0 + 4);
        float a[8] = {A0.x, A0.y, A0.z, A0.w, A1.x, A1.y, A1.z, A1.w};
        float b[8] = {B0.x, B0.y, B0.z, B0.w, B1.x, B1.y, B1.z, B1.w};
#pragma unroll
        for (int u = 0; u < 8; u++)
#pragma unroll
            for (int v = 0; v < 8; v++) acc[u][v] += a[u] * b[v];
    }

    float sQK = 0.f, sQK2 = 0.f;
#pragma unroll
    for (int u = 0; u < 8; u++)
#pragma unroll
        for (int v = 0; v < 8; v++) { float q = acc[u][v]; sQK += q; sQK2 += q * q; }

    sQK = warpSum(sQK); sQK2 = warpSum(sQK2);
    sQE = warpSum(sQE); sQE2 = warpSum(sQE2);
    sKE = warpSum(sKE); sKE2 = warpSum(sKE2);
    int w = t >> 5, lane = t & 31;
    float* red = sq;  // safe to reuse after fill phase
    if (lane == 0) {
        red[w * 8 + 0] = sQK; red[w * 8 + 1] = sQK2;
        red[w * 8 + 2] = sQE; red[w * 8 + 3] = sQE2;
        red[w * 8 + 4] = sKE; red[w * 8 + 5] = sKE2;
    }
    __syncthreads();
    if (t < 6) {
        float tot = 0.f;
        for (int i = 0; i < 8; i++) tot += red[i * 8 + t];
        int ch = (t < 2) ? g : (t < 4) ? (16 + g) : (32 + g);
        atomicAdd(&g_simStats[ch * 2 + (t & 1)], tot);
    }

    float* dst = g_qk + ((size_t)bh * 16 + g) * 16384;
#pragma unroll
    for (int u = 0; u < 8; u++) {
        *(float4*)(dst + (i0 + u) * 128 + j0)     = make_float4(acc[u][0], acc[u][1], acc[u][2], acc[u][3]);
        *(float4*)(dst + (i0 + u) * 128 + j0 + 4) = make_float4(acc[u][4], acc[u][5], acc[u][6], acc[u][7]);
    }
}

// ---------------- D: finalize sim BN scales (beta/mean cancel in softmax) -------------
__global__ void kD(const float* __restrict__ gamma_sim) {
    int t = threadIdx.x;
    if (t < 48) {
        const float N = 2097152.f;
        float S = g_simStats[t * 2], S2 = g_simStats[t * 2 + 1];
        float mean = S / N;
        float var = S2 / N - mean * mean;
        g_simScale[t] = gamma_sim[t] * rsqrtf(var + EPSF);
    }
}

// ---------------- E: sim -> softmax -> am/ame + out stats ----------------
// grid (g=16, bh=128), 256 thr
__global__ __launch_bounds__(256) void kE(const float* __restrict__ relemb) {
    extern __shared__ float sm[];
    float* sre  = sm;            // [16][256]  rel_emb rows 0..15
    float* sq   = sm + 4096;     // [4][128]
    float* sk   = sm + 4608;     // [4][128]
    float* sv   = sm + 5120;     // [8][128]
    float* ssim = sm + 6144;     // [128][132]
    const int g = blockIdx.x, bh = blockIdx.y, t = threadIdx.x;

    for (int n = t; n < 16 * 255; n += 256) {
        int r = n / 255, c = n - r * 255;
        sre[r * 256 + c] = relemb[n];
    }
    for (int n = t; n < 2048; n += 256) {
        int cl = n >> 7, m = n & 127;
        int o = g * 16 + cl;
        float v = g_qkv[(size_t)bh * 32768 + o * 128 + m] * g_scaleQ[o] + g_shiftQ[o];
        if (cl < 4) sq[cl * 128 + m] = v;
        else if (cl < 8) sk[(cl - 4) * 128 + m] = v;
        else sv[(cl - 8) * 128 + m] = v;
    }
    __syncthreads();

    const float a1 = g_simScale[g], a2 = g_simScale[16 + g], a3 = g_simScale[32 + g];
    const float* qkb = g_qk + ((size_t)bh * 16 + g) * 16384;
    for (int e = 0; e < 64; e++) {
        int idx = e * 256 + t;
        int i = idx >> 7, j = idx & 127;
        int d = i - j + 127;
        float qe = sq[i] * sre[d] + sq[128 + i] * sre[256 + d] +
                   sq[256 + i] * sre[512 + d] + sq[384 + i] * sre[768 + d];
        float ke = sk[i] * sre[1024 + d] + sk[128 + i] * sre[1280 + d] +
                   sk[256 + i] * sre[1536 + d] + sk[384 + i] * sre[1792 + d];
        ssim[i * 132 + j] = a1 * qkb[idx] + a2 * qe + a3 * ke;
    }
    __syncthreads();

    // softmax over j, one row per warp-iteration
    const int w = t >> 5, lane = t & 31;
    for (int r = 0; r < 16; r++) {
        int i = w * 16 + r;
        float4 xv = *(float4*)(ssim + i * 132 + lane * 4);
        float mx = fmaxf(fmaxf(xv.x, xv.y), fmaxf(xv.z, xv.w));
#pragma unroll
        for (int o = 16; o > 0; o >>= 1) mx = fmaxf(mx, __shfl_xor_sync(0xffffffffu, mx, o));
        float e0 = __expf(xv.x - mx), e1 = __expf(xv.y - mx);
        float e2 = __expf(xv.z - mx), e3 = __expf(xv.w - mx);
        float s = warpSum(e0 + e1 + e2 + e3);
        float inv = 1.f / s;
        *(float4*)(ssim + i * 132 + lane * 4) = make_float4(e0 * inv, e1 * inv, e2 * inv, e3 * inv);
    }
    __syncthreads();

    // am[c,i] = sum_j p[i,j] v[c,j];  ame[c,i] = sum_j p[i,j] rel_v[c, i-j+127]
    const int i = t & 127, cg = t >> 7;
    float accA[4] = {0.f, 0.f, 0.f, 0.f}, accE[4] = {0.f, 0.f, 0.f, 0.f};
    const float* srev = sre + 2048;  // rows 8..15
    for (int j = 0; j < 128; j++) {
        float p = ssim[i * 132 + j];
        int d = i - j + 127;
#pragma unroll
        for (int cc = 0; cc < 4; cc++) {
            int c = cg * 4 + cc;
            accA[cc] += p * sv[c * 128 + j];
            accE[cc] += p * srev[c * 256 + d];
        }
    }

    float* dst = g_outraw + (size_t)bh * 32768;
#pragma unroll
    for (int cc = 0; cc < 4; cc++) {
        int c = cg * 4 + cc;
        int o = g * 16 + 2 * c;
        dst[o * 128 + i] = accA[cc];
        dst[(o + 1) * 128 + i] = accE[cc];
        float sA = warpSum(accA[cc]);
        float sA2 = warpSum(accA[cc] * accA[cc]);
        float sE = warpSum(accE[cc]);
        float sE2 = warpSum(accE[cc] * accE[cc]);
        if (lane == 0) {
            atomicAdd(&g_outStats[o * 2], sA);
            atomicAdd(&g_outStats[o * 2 + 1], sA2);
            atomicAdd(&g_outStats[(o + 1) * 2], sE);
            atomicAdd(&g_outStats[(o + 1) * 2 + 1], sE2);
        }
    }
}

// ---------------- F: finalize out BN params ----------------
__global__ void kF(const float* __restrict__ gamma_out, const float* __restrict__ beta_out) {
    int o = threadIdx.x;  // 256
    const float N = 16384.f;
    float S = g_outStats[o * 2], S2 = g_outStats[o * 2 + 1];
    float mean = S / N;
    float var = S2 / N - mean * mean;
    float sc = gamma_out[o] * rsqrtf(var + EPSF);
    g_outScale[o] = sc;
    g_outShift[o] = beta_out[o] - mean * sc;
}

// ---------------- G: y[b0,oc,h,w] = bn(out)[2oc] + bn(out)[2oc+1] ----------------
__global__ __launch_bounds__(256) void kG(float* __restrict__ y) {
    int idx = blockIdx.x * 256 + threadIdx.x;  // 2097152 total
    int wpos = idx & 127;
    int h = (idx >> 7) & 63;
    int oc = (idx >> 13) & 127;
    int b0 = idx >> 20;
    int bh = b0 * 64 + h;
    int o = oc * 2;
    float v0 = g_outraw[(size_t)bh * 32768 + o * 128 + wpos];
    float v1 = g_outraw[(size_t)bh * 32768 + (o + 1) * 128 + wpos];
    y[idx] = (v0 * g_outScale[o] + g_outShift[o]) + (v1 * g_outScale[o + 1] + g_outShift[o + 1]);
}

// ---------------- launch ----------------
extern "C" void kernel_launch(void* const* d_in, const int* in_sizes, int n_in,
                              void* d_out, int out_size) {
    const float* x  = (const float*)d_in[0];
    const float* W  = (const float*)d_in[1];
    const float* gq = (const float*)d_in[2];
    const float* bq = (const float*)d_in[3];
    const float* re = (const float*)d_in[4];
    const float* gs = (const float*)d_in[5];
    // beta_sim (d_in[6]) cancels inside softmax — unused
    const float* go = (const float*)d_in[7];
    const float* bo = (const float*)d_in[8];
    float* y = (float*)d_out;

    const int SMEM_A = 2 * 128 * 132 * 4;                         // 135168
    const int SMEM_C = (2048 + 512 + 512 + 16896 + 16896) * 4;    // 147456
    const int SMEM_E = (4096 + 512 + 512 + 1024 + 16896) * 4;     // 92160

    cudaFuncSetAttribute(kA, cudaFuncAttributeMaxDynamicSharedMemorySize, SMEM_A);
    cudaFuncSetAttribute(kC, cudaFuncAttributeMaxDynamicSharedMemorySize, SMEM_C);
    cudaFuncSetAttribute(kE, cudaFuncAttributeMaxDynamicSharedMemorySize, SMEM_E);

    kZero<<<1, 256>>>();
    kA<<<dim3(2, 128), 256, SMEM_A>>>(x, W);
    kB<<<256, 256>>>(gq, bq);
    kC<<<dim3(16, 128), 256, SMEM_C>>>(re);
    kD<<<1, 64>>>(gs);
    kE<<<dim3(16, 128), 256, SMEM_E>>>(re);
    kF<<<1, 256>>>(go, bo);
    kG<<<8192, 256>>>(y);
}

// round 3
// speedup vs baseline: 1.4179x; 1.4179x over previous
#include <cuda_runtime.h>
#include <math.h>
#include <stdint.h>

#define EPSF 1e-5f

// ---------------- scratch (device globals; no allocation allowed) ----------------
__device__ float g_qkv[4194304];      // [128 bh][256 o][128 l]  raw qkv (pre-BN)
__device__ float g_outraw[4194304];   // [128 bh][256 o][128 i]  raw am/ame (pre-BN)
__device__ float g_simStats[96];      // [48 ch][sum, sumsq]
__device__ float g_outStats[512];     // [256 ch][sum, sumsq]
__device__ float g_scaleQ[256];
__device__ float g_shiftQ[256];
__device__ float g_simScale[48];
__device__ float g_outScale[256];
__device__ float g_outShift[256];

__device__ __forceinline__ float warpSum(float v) {
#pragma unroll
    for (int o = 16; o > 0; o >>= 1) v += __shfl_xor_sync(0xffffffffu, v, o);
    return v;
}

__device__ __forceinline__ uint32_t tf32r(float x) {
    uint32_t u;
    asm("cvt.rna.tf32.f32 %0, %1;" : "=r"(u) : "f"(x));
    return u;
}

__device__ __forceinline__ void mma8(float* c, const uint32_t* a, uint32_t b0, uint32_t b1) {
    asm volatile(
        "mma.sync.aligned.m16n8k8.row.col.f32.tf32.tf32.f32 "
        "{%0,%1,%2,%3},{%4,%5,%6,%7},{%8,%9},{%0,%1,%2,%3};\n"
        : "+f"(c[0]), "+f"(c[1]), "+f"(c[2]), "+f"(c[3])
        : "r"(a[0]), "r"(a[1]), "r"(a[2]), "r"(a[3]), "r"(b0), "r"(b1));
}

// ---------------- Z: zero stat accumulators ----------------
__global__ void kZero() {
    int t = threadIdx.x;
    if (t < 96) g_simStats[t] = 0.f;
    g_outStats[t] = 0.f;
    g_outStats[t + 256] = 0.f;
}

// ---------------- A: qkv[bh,o,l] = sum_c W[o,c] * x[b0,c,h,l] ----------------
__global__ __launch_bounds__(256) void kA(const float* __restrict__ x,
                                          const float* __restrict__ W) {
    extern __shared__ float sm[];
    float* sa = sm;              // [128 k][132]
    float* sb = sm + 16896;      // [128 k][132]
    const int ot = blockIdx.x, bh = blockIdx.y;
    const int b0 = bh >> 6, h = bh & 63;
    const int t = threadIdx.x;

    for (int e = 0; e < 64; e++) {
        int idx = e * 256 + t;
        int r = idx >> 7, c = idx & 127;
        sa[c * 132 + r] = W[(ot * 128 + r) * 128 + c];
    }
    for (int e = 0; e < 64; e++) {
        int idx = e * 256 + t;
        int c = idx >> 7, l = idx & 127;
        sb[c * 132 + l] = x[((b0 * 128 + c) * 64 + h) * 128 + l];
    }
    __syncthreads();

    const int ty = t >> 4, tx = t & 15;
    const int i0 = ty * 8, j0 = tx * 8;
    float acc[8][8];
#pragma unroll
    for (int u = 0; u < 8; u++)
#pragma unroll
        for (int v = 0; v < 8; v++) acc[u][v] = 0.f;

#pragma unroll 2
    for (int k = 0; k < 128; k++) {
        float4 A0 = *(const float4*)(sa + k * 132 + i0);
        float4 A1 = *(const float4*)(sa + k * 132 + i0 + 4);
        float4 B0 = *(const float4*)(sb + k * 132 + j0);
        float4 B1 = *(const float4*)(sb + k * 132 + j0 + 4);
        float a[8] = {A0.x, A0.y, A0.z, A0.w, A1.x, A1.y, A1.z, A1.w};
        float b[8] = {B0.x, B0.y, B0.z, B0.w, B1.x, B1.y, B1.z, B1.w};
#pragma unroll
        for (int u = 0; u < 8; u++)
#pragma unroll
            for (int v = 0; v < 8; v++) acc[u][v] += a[u] * b[v];
    }

    float* dst = g_qkv + (size_t)bh * 32768 + (size_t)(ot * 128) * 128;
#pragma unroll
    for (int u = 0; u < 8; u++) {
        *(float4*)(dst + (i0 + u) * 128 + j0)     = make_float4(acc[u][0], acc[u][1], acc[u][2], acc[u][3]);
        *(float4*)(dst + (i0 + u) * 128 + j0 + 4) = make_float4(acc[u][4], acc[u][5], acc[u][6], acc[u][7]);
    }
}

// ---------------- B: per-channel BN stats for qkv ----------------
__global__ __launch_bounds__(256) void kB(const float* __restrict__ gamma,
                                          const float* __restrict__ beta) {
    const int o = blockIdx.x, t = threadIdx.x;
    float s = 0.f, s2 = 0.f;
    for (int e = 0; e < 64; e++) {
        int n = e * 256 + t;
        float v = g_qkv[(size_t)(n >> 7) * 32768 + o * 128 + (n & 127)];
        s += v; s2 += v * v;
    }
    s = warpSum(s); s2 = warpSum(s2);
    __shared__ float rs[8], rs2[8];
    int w = t >> 5, lane = t & 31;
    if (lane == 0) { rs[w] = s; rs2[w] = s2; }
    __syncthreads();
    if (t == 0) {
        float S = 0.f, S2 = 0.f;
        for (int i = 0; i < 8; i++) { S += rs[i]; S2 += rs2[i]; }
        float mean = S * (1.f / 16384.f);
        float var  = S2 * (1.f / 16384.f) - mean * mean;
        float sc = gamma[o] * rsqrtf(var + EPSF);
        g_scaleQ[o] = sc;
        g_shiftQ[o] = beta[o] - mean * sc;
    }
}

// ---------------- C: fill qe/ke (tf32-rounded), TC qk, sim stats (no qk store) -------
// grid (g=16, bh=128), 256 thr
__global__ __launch_bounds__(256) void kC(const float* __restrict__ relemb) {
    extern __shared__ float sm[];
    float* sreq = sm;            // [255][4] interleaved q rel rows 0..3
    float* srek = sm + 1024;     // [255][4] k rel rows 4..7
    float* sq4  = sm + 2048;     // [128][4]
    float* sk4  = sm + 2560;     // [128][4]
    float* sqe  = sm + 3072;     // [128][136] qe[m][i] (tf32-rounded fp32)
    float* ske  = sm + 20480;    // [128][136] ke[m][j]
    const int g = blockIdx.x, bh = blockIdx.y, t = threadIdx.x;
    const int lane = t & 31, w = t >> 5;

    for (int n = t; n < 1020; n += 256) {
        int c = n & 3, d = n >> 2;
        sreq[n] = relemb[c * 255 + d];
        srek[n] = relemb[(4 + c) * 255 + d];
    }
    for (int n = t; n < 1024; n += 256) {
        int c8 = n >> 7, m = n & 127;
        int o = g * 16 + c8;
        float v = g_qkv[(size_t)bh * 32768 + o * 128 + m] * g_scaleQ[o] + g_shiftQ[o];
        if (c8 < 4) sq4[m * 4 + c8] = v; else sk4[m * 4 + c8 - 4] = v;
    }
    __syncthreads();

    float sQE = 0.f, sQE2 = 0.f, sKE = 0.f, sKE2 = 0.f;
    for (int e = 0; e < 64; e++) {
        int idx = e * 256 + t;
        int m = idx >> 7, i = idx & 127;
        int d = m - i + 127;
        float4 qv = *(const float4*)(sq4 + 4 * m);
        float4 rq = *(const float4*)(sreq + 4 * d);
        float4 kv = *(const float4*)(sk4 + 4 * m);
        float4 rk = *(const float4*)(srek + 4 * d);
        float qe = qv.x * rq.x + qv.y * rq.y + qv.z * rq.z + qv.w * rq.w;
        float ke = kv.x * rk.x + kv.y * rk.y + kv.z * rk.z + kv.w * rk.w;
        sQE += qe; sQE2 += qe * qe; sKE += ke; sKE2 += ke * ke;
        sqe[m * 136 + i] = __uint_as_float(tf32r(qe));
        ske[m * 136 + i] = __uint_as_float(tf32r(ke));
    }
    __syncthreads();

    // qk = qe^T * ke via tf32 mma. warp tile 32(i) x 64(j)
    const int i0w = (w >> 1) * 32, j0w = (w & 1) * 64;
    const int rw = lane >> 2, cl = lane & 3;
    float c[2][8][4];
#pragma unroll
    for (int ii = 0; ii < 2; ii++)
#pragma unroll
        for (int jj = 0; jj < 8; jj++)
#pragma unroll
            for (int u = 0; u < 4; u++) c[ii][jj][u] = 0.f;

    for (int kc = 0; kc < 16; kc++) {
        const int k0 = kc * 8;
        uint32_t a[2][4];
#pragma unroll
        for (int ii = 0; ii < 2; ii++) {
            const float* base = sqe + (k0 + cl) * 136 + i0w + ii * 16 + rw;
            a[ii][0] = __float_as_uint(base[0]);
            a[ii][1] = __float_as_uint(base[8]);
            a[ii][2] = __float_as_uint(base[4 * 136]);
            a[ii][3] = __float_as_uint(base[4 * 136 + 8]);
        }
#pragma unroll
        for (int jj = 0; jj < 8; jj++) {
            const float* bb = ske + (k0 + cl) * 136 + j0w + jj * 8 + rw;
            uint32_t b0 = __float_as_uint(bb[0]);
            uint32_t b1 = __float_as_uint(bb[4 * 136]);
            mma8(c[0][jj], a[0], b0, b1);
            mma8(c[1][jj], a[1], b0, b1);
        }
    }

    float sQK = 0.f, sQK2 = 0.f;
#pragma unroll
    for (int ii = 0; ii < 2; ii++)
#pragma unroll
        for (int jj = 0; jj < 8; jj++)
#pragma unroll
            for (int u = 0; u < 4; u++) { float q = c[ii][jj][u]; sQK += q; sQK2 += q * q; }

    sQK = warpSum(sQK); sQK2 = warpSum(sQK2);
    sQE = warpSum(sQE); sQE2 = warpSum(sQE2);
    sKE = warpSum(sKE); sKE2 = warpSum(sKE2);
    float* red = sq4;  // reuse
    if (lane == 0) {
        red[w * 8 + 0] = sQK; red[w * 8 + 1] = sQK2;
        red[w * 8 + 2] = sQE; red[w * 8 + 3] = sQE2;
        red[w * 8 + 4] = sKE; red[w * 8 + 5] = sKE2;
    }
    __syncthreads();
    if (t < 6) {
        float tot = 0.f;
        for (int i = 0; i < 8; i++) tot += red[i * 8 + t];
        int ch = (t < 2) ? g : (t < 4) ? (16 + g) : (32 + g);
        atomicAdd(&g_simStats[ch * 2 + (t & 1)], tot);
    }
}

// ---------------- D: finalize sim BN scales ----------------
__global__ void kD(const float* __restrict__ gamma_sim) {
    int t = threadIdx.x;
    if (t < 48) {
        const float N = 2097152.f;
        float S = g_simStats[t * 2], S2 = g_simStats[t * 2 + 1];
        float mean = S / N;
        float var = S2 / N - mean * mean;
        g_simScale[t] = gamma_sim[t] * rsqrtf(var + EPSF);
    }
}

// ---------------- E: recompute qk (TC), sim -> softmax -> am/ame + out stats --------
// grid (g=16, bh=128), 256 thr
__global__ __launch_bounds__(256) void kE(const float* __restrict__ relemb) {
    extern __shared__ float sm[];
    float* sreq = sm;            // [255][4]
    float* srek = sm + 1024;
    float* srva = sm + 2048;     // v rel rows 8..11
    float* srvb = sm + 3072;     // v rel rows 12..15
    float* sq4  = sm + 4096;     // [128][4]
    float* sk4  = sm + 4608;
    float* sva4 = sm + 5120;     // v ch 0..3  [j][4]
    float* svb4 = sm + 5632;     // v ch 4..7
    float* sqe  = sm + 6144;     // [128][136] qe[m][i] unrounded; later aliased by ssim
    float* ske  = sm + 23552;    // [128][136]
    float* ssim = sqe;           // [128][133] after combine
    const int g = blockIdx.x, bh = blockIdx.y, t = threadIdx.x;
    const int lane = t & 31, w = t >> 5;

    for (int n = t; n < 1020; n += 256) {
        int c = n & 3, d = n >> 2;
        sreq[n] = relemb[c * 255 + d];
        srek[n] = relemb[(4 + c) * 255 + d];
        srva[n] = relemb[(8 + c) * 255 + d];
        srvb[n] = relemb[(12 + c) * 255 + d];
    }
    for (int n = t; n < 2048; n += 256) {
        int c8 = n >> 7, m = n & 127;
        int o = g * 16 + c8;
        float v = g_qkv[(size_t)bh * 32768 + o * 128 + m] * g_scaleQ[o] + g_shiftQ[o];
        if (c8 < 4)       sq4[m * 4 + c8] = v;
        else if (c8 < 8)  sk4[m * 4 + c8 - 4] = v;
        else if (c8 < 12) sva4[m * 4 + c8 - 8] = v;
        else              svb4[m * 4 + c8 - 12] = v;
    }
    __syncthreads();

    for (int e = 0; e < 64; e++) {
        int idx = e * 256 + t;
        int m = idx >> 7, i = idx & 127;
        int d = m - i + 127;
        float4 qv = *(const float4*)(sq4 + 4 * m);
        float4 rq = *(const float4*)(sreq + 4 * d);
        float4 kv = *(const float4*)(sk4 + 4 * m);
        float4 rk = *(const float4*)(srek + 4 * d);
        sqe[m * 136 + i] = qv.x * rq.x + qv.y * rq.y + qv.z * rq.z + qv.w * rq.w;
        ske[m * 136 + i] = kv.x * rk.x + kv.y * rk.y + kv.z * rk.z + kv.w * rk.w;
    }
    __syncthreads();

    const int i0w = (w >> 1) * 32, j0w = (w & 1) * 64;
    const int rw = lane >> 2, cl = lane & 3;
    float c[2][8][4];
#pragma unroll
    for (int ii = 0; ii < 2; ii++)
#pragma unroll
        for (int jj = 0; jj < 8; jj++)
#pragma unroll
            for (int u = 0; u < 4; u++) c[ii][jj][u] = 0.f;

    for (int kc = 0; kc < 16; kc++) {
        const int k0 = kc * 8;
        uint32_t a[2][4];
#pragma unroll
        for (int ii = 0; ii < 2; ii++) {
            const float* base = sqe + (k0 + cl) * 136 + i0w + ii * 16 + rw;
            a[ii][0] = tf32r(base[0]);
            a[ii][1] = tf32r(base[8]);
            a[ii][2] = tf32r(base[4 * 136]);
            a[ii][3] = tf32r(base[4 * 136 + 8]);
        }
#pragma unroll
        for (int jj = 0; jj < 8; jj++) {
            const float* bb = ske + (k0 + cl) * 136 + j0w + jj * 8 + rw;
            uint32_t b0 = tf32r(bb[0]);
            uint32_t b1 = tf32r(bb[4 * 136]);
            mma8(c[0][jj], a[0], b0, b1);
            mma8(c[1][jj], a[1], b0, b1);
        }
    }

    // combine: sim = a1*qk + a2*qe(i,j) + a3*ke(i,j)   (reads sqe/ske at frag coords)
    const float a1 = g_simScale[g], a2 = g_simScale[16 + g], a3 = g_simScale[32 + g];
#pragma unroll
    for (int ii = 0; ii < 2; ii++)
#pragma unroll
        for (int jj = 0; jj < 8; jj++) {
            int ir0 = i0w + ii * 16 + rw;
            int jc = j0w + jj * 8 + 2 * cl;
            float2 q0 = *(const float2*)(sqe + ir0 * 136 + jc);
            float2 k0 = *(const float2*)(ske + ir0 * 136 + jc);
            float2 q1 = *(const float2*)(sqe + (ir0 + 8) * 136 + jc);
            float2 k1 = *(const float2*)(ske + (ir0 + 8) * 136 + jc);
            float* cc = c[ii][jj];
            cc[0] = a1 * cc[0] + a2 * q0.x + a3 * k0.x;
            cc[1] = a1 * cc[1] + a2 * q0.y + a3 * k0.y;
            cc[2] = a1 * cc[2] + a2 * q1.x + a3 * k1.x;
            cc[3] = a1 * cc[3] + a2 * q1.y + a3 * k1.y;
        }
    __syncthreads();   // all sqe/ske reads done; safe to overwrite with ssim

#pragma unroll
    for (int ii = 0; ii < 2; ii++)
#pragma unroll
        for (int jj = 0; jj < 8; jj++) {
            int ir0 = i0w + ii * 16 + rw;
            int jc = j0w + jj * 8 + 2 * cl;
            float* cc = c[ii][jj];
            ssim[ir0 * 133 + jc] = cc[0];
            ssim[ir0 * 133 + jc + 1] = cc[1];
            ssim[(ir0 + 8) * 133 + jc] = cc[2];
            ssim[(ir0 + 8) * 133 + jc + 1] = cc[3];
        }
    __syncthreads();

    // softmax over j (row per warp-iteration; pitch 133 -> conflict-free columns later)
    for (int r = 0; r < 16; r++) {
        int i = w * 16 + r;
        float* row = ssim + i * 133;
        float x0 = row[lane], x1 = row[lane + 32], x2 = row[lane + 64], x3 = row[lane + 96];
        float mx = fmaxf(fmaxf(x0, x1), fmaxf(x2, x3));
#pragma unroll
        for (int o = 16; o > 0; o >>= 1) mx = fmaxf(mx, __shfl_xor_sync(0xffffffffu, mx, o));
        float e0 = __expf(x0 - mx), e1 = __expf(x1 - mx);
        float e2 = __expf(x2 - mx), e3 = __expf(x3 - mx);
        float s = warpSum(e0 + e1 + e2 + e3);
        float inv = 1.f / s;
        row[lane] = e0 * inv; row[lane + 32] = e1 * inv;
        row[lane + 64] = e2 * inv; row[lane + 96] = e3 * inv;
    }
    __syncthreads();

    // am/ame: thread owns (i, channel-group)
    const int i = t & 127, cg = t >> 7;
    const float* svp = (cg == 0) ? sva4 : svb4;
    const float* srv = (cg == 0) ? srva : srvb;
    float accA[4] = {0.f, 0.f, 0.f, 0.f}, accE[4] = {0.f, 0.f, 0.f, 0.f};
    for (int j = 0; j < 128; j++) {
        float p = ssim[i * 133 + j];
        int d = i - j + 127;
        float4 v4 = *(const float4*)(svp + 4 * j);
        float4 r4 = *(const float4*)(srv + 4 * d);
        accA[0] += p * v4.x; accA[1] += p * v4.y; accA[2] += p * v4.z; accA[3] += p * v4.w;
        accE[0] += p * r4.x; accE[1] += p * r4.y; accE[2] += p * r4.z; accE[3] += p * r4.w;
    }

    float* dst = g_outraw + (size_t)bh * 32768;
#pragma unroll
    for (int cc = 0; cc < 4; cc++) {
        int ch = cg * 4 + cc;
        int o = g * 16 + 2 * ch;
        dst[o * 128 + i] = accA[cc];
        dst[(o + 1) * 128 + i] = accE[cc];
        float sA = warpSum(accA[cc]);
        float sA2 = warpSum(accA[cc] * accA[cc]);
        float sE = warpSum(accE[cc]);
        float sE2 = warpSum(accE[cc] * accE[cc]);
        if (lane == 0) {
            atomicAdd(&g_outStats[o * 2], sA);
            atomicAdd(&g_outStats[o * 2 + 1], sA2);
            atomicAdd(&g_outStats[(o + 1) * 2], sE);
            atomicAdd(&g_outStats[(o + 1) * 2 + 1], sE2);
        }
    }
}

// ---------------- F: finalize out BN params ----------------
__global__ void kF(const float* __restrict__ gamma_out, const float* __restrict__ beta_out) {
    int o = threadIdx.x;  // 256
    const float N = 16384.f;
    float S = g_outStats[o * 2], S2 = g_outStats[o * 2 + 1];
    float mean = S / N;
    float var = S2 / N - mean * mean;
    float sc = gamma_out[o] * rsqrtf(var + EPSF);
    g_outScale[o] = sc;
    g_outShift[o] = beta_out[o] - mean * sc;
}

// ---------------- G: y = bn(out)[2oc] + bn(out)[2oc+1], transpose-write -------------
__global__ __launch_bounds__(256) void kG(float* __restrict__ y) {
    int idx = blockIdx.x * 256 + threadIdx.x;
    int wpos = idx & 127;
    int h = (idx >> 7) & 63;
    int oc = (idx >> 13) & 127;
    int b0 = idx >> 20;
    int bh = b0 * 64 + h;
    int o = oc * 2;
    float v0 = g_outraw[(size_t)bh * 32768 + o * 128 + wpos];
    float v1 = g_outraw[(size_t)bh * 32768 + (o + 1) * 128 + wpos];
    y[idx] = (v0 * g_outScale[o] + g_outShift[o]) + (v1 * g_outScale[o + 1] + g_outShift[o + 1]);
}

// ---------------- launch ----------------
extern "C" void kernel_launch(void* const* d_in, const int* in_sizes, int n_in,
                              void* d_out, int out_size) {
    const float* x  = (const float*)d_in[0];
    const float* W  = (const float*)d_in[1];
    const float* gq = (const float*)d_in[2];
    const float* bq = (const float*)d_in[3];
    const float* re = (const float*)d_in[4];
    const float* gs = (const float*)d_in[5];
    // beta_sim (d_in[6]) cancels inside softmax — unused
    const float* go = (const float*)d_in[7];
    const float* bo = (const float*)d_in[8];
    float* y = (float*)d_out;

    const int SMEM_A = 2 * 128 * 132 * 4;            // 135168
    const int SMEM_C = (20480 + 17408) * 4;          // 151552
    const int SMEM_E = (23552 + 17408) * 4;          // 163840

    cudaFuncSetAttribute(kA, cudaFuncAttributeMaxDynamicSharedMemorySize, SMEM_A);
    cudaFuncSetAttribute(kC, cudaFuncAttributeMaxDynamicSharedMemorySize, SMEM_C);
    cudaFuncSetAttribute(kE, cudaFuncAttributeMaxDynamicSharedMemorySize, SMEM_E);

    kZero<<<1, 256>>>();
    kA<<<dim3(2, 128), 256, SMEM_A>>>(x, W);
    kB<<<256, 256>>>(gq, bq);
    kC<<<dim3(16, 128), 256, SMEM_C>>>(re);
    kD<<<1, 64>>>(gs);
    kE<<<dim3(16, 128), 256, SMEM_E>>>(re);
    kF<<<1, 256>>>(go, bo);
    kG<<<8192, 256>>>(y);
}

// round 5
// speedup vs baseline: 1.4312x; 1.0094x over previous
#include <cuda_runtime.h>
#include <math.h>
#include <stdint.h>

#define EPSF 1e-5f

// ---------------- scratch (device globals) ----------------
__device__ float g_qkv[4194304];      // [128 bh][256 o][128 l]
__device__ float g_outraw[4194304];   // [128 bh][256 o][128 i]
__device__ float g_qkvStats[512];     // [256 ch][sum,sumsq]
__device__ float g_simStats[96];
__device__ float g_outStats[512];
__device__ float g_scaleQ[256];
__device__ float g_shiftQ[256];
__device__ float g_simScale[48];
__device__ float g_outScale[256];
__device__ float g_outShift[256];

__device__ __forceinline__ float warpSum(float v) {
#pragma unroll
    for (int o = 16; o > 0; o >>= 1) v += __shfl_xor_sync(0xffffffffu, v, o);
    return v;
}

__device__ __forceinline__ float halfWarpSum(float v) {
#pragma unroll
    for (int o = 8; o > 0; o >>= 1) v += __shfl_xor_sync(0xffffffffu, v, o);
    return v;
}

__device__ __forceinline__ uint32_t tf32r(float x) {
    uint32_t u;
    asm("cvt.rna.tf32.f32 %0, %1;" : "=r"(u) : "f"(x));
    return u;
}

__device__ __forceinline__ void mma8(float* c, const uint32_t* a, uint32_t b0, uint32_t b1) {
    asm volatile(
        "mma.sync.aligned.m16n8k8.row.col.f32.tf32.tf32.f32 "
        "{%0,%1,%2,%3},{%4,%5,%6,%7},{%8,%9},{%0,%1,%2,%3};\n"
        : "+f"(c[0]), "+f"(c[1]), "+f"(c[2]), "+f"(c[3])
        : "r"(a[0]), "r"(a[1]), "r"(a[2]), "r"(a[3]), "r"(b0), "r"(b1));
}

// ---------------- Z: zero stat accumulators ----------------
__global__ void kZero() {
    int t = threadIdx.x;  // 512
    if (t < 96) g_simStats[t] = 0.f;
    g_outStats[t & 511] = 0.f;
    g_qkvStats[t & 511] = 0.f;
}

// ---------------- A: qkv GEMM (j-half split) + fused BN stats ----------------
// grid (4, 128): bx = ot*2 + jh. 256 thr. smem ~101KB -> 2 CTAs/SM.
__global__ __launch_bounds__(256) void kA(const float* __restrict__ x,
                                          const float* __restrict__ W) {
    extern __shared__ float sm[];
    float* sa = sm;              // [128 k][132]  W^T tile (k-major)
    float* sb = sm + 16896;      // [128 k][68]   x tile (j-half)
    const int ot = blockIdx.x >> 1, jh = blockIdx.x & 1, bh = blockIdx.y;
    const int b0 = bh >> 6, h = bh & 63;
    const int t = threadIdx.x;

    for (int e = 0; e < 64; e++) {
        int idx = e * 256 + t;
        int r = idx >> 7, c = idx & 127;
        sa[c * 132 + r] = W[(ot * 128 + r) * 128 + c];
    }
    for (int e = 0; e < 32; e++) {
        int idx = e * 256 + t;
        int c = idx >> 6, l0 = idx & 63;
        sb[c * 68 + l0] = x[((b0 * 128 + c) * 64 + h) * 128 + jh * 64 + l0];
    }
    __syncthreads();

    const int ty = t >> 4, tx = t & 15;
    const int i0 = ty * 8, j0 = tx * 4;
    float acc[8][4];
#pragma unroll
    for (int u = 0; u < 8; u++)
#pragma unroll
        for (int v = 0; v < 4; v++) acc[u][v] = 0.f;

#pragma unroll 2
    for (int k = 0; k < 128; k++) {
        float4 A0 = *(const float4*)(sa + k * 132 + i0);
        float4 A1 = *(const float4*)(sa + k * 132 + i0 + 4);
        float4 B0 = *(const float4*)(sb + k * 68 + j0);
        float a[8] = {A0.x, A0.y, A0.z, A0.w, A1.x, A1.y, A1.z, A1.w};
        float b[4] = {B0.x, B0.y, B0.z, B0.w};
#pragma unroll
        for (int u = 0; u < 8; u++)
#pragma unroll
            for (int v = 0; v < 4; v++) acc[u][v] += a[u] * b[v];
    }

    float* dst = g_qkv + (size_t)bh * 32768 + (size_t)(ot * 128) * 128 + jh * 64;
    const int lane = t & 31;
#pragma unroll
    for (int u = 0; u < 8; u++) {
        *(float4*)(dst + (i0 + u) * 128 + j0) = make_float4(acc[u][0], acc[u][1], acc[u][2], acc[u][3]);
        float s = acc[u][0] + acc[u][1] + acc[u][2] + acc[u][3];
        float s2 = acc[u][0] * acc[u][0] + acc[u][1] * acc[u][1] +
                   acc[u][2] * acc[u][2] + acc[u][3] * acc[u][3];
        s = halfWarpSum(s);
        s2 = halfWarpSum(s2);
        if ((lane & 15) == 0) {
            int ch = ot * 128 + i0 + u;
            atomicAdd(&g_qkvStats[ch * 2], s);
            atomicAdd(&g_qkvStats[ch * 2 + 1], s2);
        }
    }
}

// ---------------- B': finalize qkv BN ----------------
__global__ void kBf(const float* __restrict__ gamma, const float* __restrict__ beta) {
    int o = threadIdx.x;  // 256
    float S = g_qkvStats[o * 2], S2 = g_qkvStats[o * 2 + 1];
    float mean = S * (1.f / 16384.f);
    float var  = S2 * (1.f / 16384.f) - mean * mean;
    float sc = gamma[o] * rsqrtf(var + EPSF);
    g_scaleQ[o] = sc;
    g_shiftQ[o] = beta[o] - mean * sc;
}

// ---------------- C: qe/ke build + TC qk + sim stats ----------------
// grid (16, 128), 512 thr
__global__ __launch_bounds__(512) void kC(const float* __restrict__ relemb) {
    extern __shared__ float sm[];
    float* sreq = sm;            // [255][4]
    float* srek = sm + 1024;
    float* sq4  = sm + 2048;     // [128][4]
    float* sk4  = sm + 2560;
    float* sqe  = sm + 3072;     // [128][136]
    float* ske  = sm + 20480;    // [128][136]
    const int g = blockIdx.x, bh = blockIdx.y, t = threadIdx.x;
    const int lane = t & 31, w = t >> 5;

    for (int n = t; n < 1020; n += 512) {
        int c = n & 3, d = n >> 2;
        sreq[n] = relemb[c * 255 + d];
        srek[n] = relemb[(4 + c) * 255 + d];
    }
    for (int n = t; n < 1024; n += 512) {
        int c8 = n >> 7, m = n & 127;
        int o = g * 16 + c8;
        float v = g_qkv[(size_t)bh * 32768 + o * 128 + m] * g_scaleQ[o] + g_shiftQ[o];
        if (c8 < 4) sq4[m * 4 + c8] = v; else sk4[m * 4 + c8 - 4] = v;
    }
    __syncthreads();

    float sQE = 0.f, sQE2 = 0.f, sKE = 0.f, sKE2 = 0.f;
    for (int e = 0; e < 32; e++) {
        int idx = e * 512 + t;
        int m = idx >> 7, i = idx & 127;
        int d = m - i + 127;
        float4 qv = *(const float4*)(sq4 + 4 * m);
        float4 rq = *(const float4*)(sreq + 4 * d);
        float4 kv = *(const float4*)(sk4 + 4 * m);
        float4 rk = *(const float4*)(srek + 4 * d);
        float qe = qv.x * rq.x + qv.y * rq.y + qv.z * rq.z + qv.w * rq.w;
        float ke = kv.x * rk.x + kv.y * rk.y + kv.z * rk.z + kv.w * rk.w;
        sQE += qe; sQE2 += qe * qe; sKE += ke; sKE2 += ke * ke;
        sqe[m * 136 + i] = __uint_as_float(tf32r(qe));
        ske[m * 136 + i] = __uint_as_float(tf32r(ke));
    }
    __syncthreads();

    // qk = qe^T * ke. 16 warps, tile 32(i) x 32(j)
    const int i0w = (w >> 2) * 32, j0w = (w & 3) * 32;
    const int rw = lane >> 2, cl = lane & 3;
    float c[2][4][4];
#pragma unroll
    for (int ii = 0; ii < 2; ii++)
#pragma unroll
        for (int jj = 0; jj < 4; jj++)
#pragma unroll
            for (int u = 0; u < 4; u++) c[ii][jj][u] = 0.f;

    for (int kc = 0; kc < 16; kc++) {
        const int k0 = kc * 8;
        uint32_t a[2][4];
#pragma unroll
        for (int ii = 0; ii < 2; ii++) {
            const float* base = sqe + (k0 + cl) * 136 + i0w + ii * 16 + rw;
            a[ii][0] = __float_as_uint(base[0]);
            a[ii][1] = __float_as_uint(base[8]);
            a[ii][2] = __float_as_uint(base[4 * 136]);
            a[ii][3] = __float_as_uint(base[4 * 136 + 8]);
        }
#pragma unroll
        for (int jj = 0; jj < 4; jj++) {
            const float* bb = ske + (k0 + cl) * 136 + j0w + jj * 8 + rw;
            uint32_t b0 = __float_as_uint(bb[0]);
            uint32_t b1 = __float_as_uint(bb[4 * 136]);
            mma8(c[0][jj], a[0], b0, b1);
            mma8(c[1][jj], a[1], b0, b1);
        }
    }

    float sQK = 0.f, sQK2 = 0.f;
#pragma unroll
    for (int ii = 0; ii < 2; ii++)
#pragma unroll
        for (int jj = 0; jj < 4; jj++)
#pragma unroll
            for (int u = 0; u < 4; u++) { float q = c[ii][jj][u]; sQK += q; sQK2 += q * q; }

    sQK = warpSum(sQK); sQK2 = warpSum(sQK2);
    sQE = warpSum(sQE); sQE2 = warpSum(sQE2);
    sKE = warpSum(sKE); sKE2 = warpSum(sKE2);
    float* red = sq4;  // reuse: 128 floats needed
    if (lane == 0) {
        red[w * 8 + 0] = sQK; red[w * 8 + 1] = sQK2;
        red[w * 8 + 2] = sQE; red[w * 8 + 3] = sQE2;
        red[w * 8 + 4] = sKE; red[w * 8 + 5] = sKE2;
    }
    __syncthreads();
    if (t < 6) {
        float tot = 0.f;
        for (int i = 0; i < 16; i++) tot += red[i * 8 + t];
        int ch = (t < 2) ? g : (t < 4) ? (16 + g) : (32 + g);
        atomicAdd(&g_simStats[ch * 2 + (t & 1)], tot);
    }
}

// ---------------- D: finalize sim BN scales ----------------
__global__ void kD(const float* __restrict__ gamma_sim) {
    int t = threadIdx.x;
    if (t < 48) {
        const float N = 2097152.f;
        float S = g_simStats[t * 2], S2 = g_simStats[t * 2 + 1];
        float mean = S / N;
        float var = S2 / N - mean * mean;
        g_simScale[t] = gamma_sim[t] * rsqrtf(var + EPSF);
    }
}

// ---------------- E: recompute qk (TC) -> sim -> softmax -> am/ame + out stats ------
// grid (16, 128), 512 thr
__global__ __launch_bounds__(512) void kE(const float* __restrict__ relemb) {
    extern __shared__ float sm[];
    float* sreq = sm;            // [255][4]
    float* srek = sm + 1024;
    float* srva = sm + 2048;     // v rel ch 0..3
    float* srvb = sm + 3072;     // v rel ch 4..7
    float* sq4  = sm + 4096;     // [128][4]
    float* sk4  = sm + 4608;
    float* sva4 = sm + 5120;     // v ch 0..3 [j][4]
    float* svb4 = sm + 5632;
    float* sqe  = sm + 6144;     // [128][136] tf32-rounded; later aliased by ssim
    float* ske  = sm + 23552;    // [128][136]
    float* ssim = sqe;           // [128][133]
    const int g = blockIdx.x, bh = blockIdx.y, t = threadIdx.x;
    const int lane = t & 31, w = t >> 5;

    for (int n = t; n < 1020; n += 512) {
        int c = n & 3, d = n >> 2;
        sreq[n] = relemb[c * 255 + d];
        srek[n] = relemb[(4 + c) * 255 + d];
        srva[n] = relemb[(8 + c) * 255 + d];
        srvb[n] = relemb[(12 + c) * 255 + d];
    }
    for (int n = t; n < 2048; n += 512) {
        int c8 = n >> 7, m = n & 127;
        int o = g * 16 + c8;
        float v = g_qkv[(size_t)bh * 32768 + o * 128 + m] * g_scaleQ[o] + g_shiftQ[o];
        if (c8 < 4)       sq4[m * 4 + c8] = v;
        else if (c8 < 8)  sk4[m * 4 + c8 - 4] = v;
        else if (c8 < 12) sva4[m * 4 + c8 - 8] = v;
        else              svb4[m * 4 + c8 - 12] = v;
    }
    __syncthreads();

    for (int e = 0; e < 32; e++) {
        int idx = e * 512 + t;
        int m = idx >> 7, i = idx & 127;
        int d = m - i + 127;
        float4 qv = *(const float4*)(sq4 + 4 * m);
        float4 rq = *(const float4*)(sreq + 4 * d);
        float4 kv = *(const float4*)(sk4 + 4 * m);
        float4 rk = *(const float4*)(srek + 4 * d);
        float qe = qv.x * rq.x + qv.y * rq.y + qv.z * rq.z + qv.w * rq.w;
        float ke = kv.x * rk.x + kv.y * rk.y + kv.z * rk.z + kv.w * rk.w;
        sqe[m * 136 + i] = __uint_as_float(tf32r(qe));
        ske[m * 136 + i] = __uint_as_float(tf32r(ke));
    }
    __syncthreads();

    const int i0w = (w >> 2) * 32, j0w = (w & 3) * 32;
    const int rw = lane >> 2, cl = lane & 3;
    float c[2][4][4];
#pragma unroll
    for (int ii = 0; ii < 2; ii++)
#pragma unroll
        for (int jj = 0; jj < 4; jj++)
#pragma unroll
            for (int u = 0; u < 4; u++) c[ii][jj][u] = 0.f;

    for (int kc = 0; kc < 16; kc++) {
        const int k0 = kc * 8;
        uint32_t a[2][4];
#pragma unroll
        for (int ii = 0; ii < 2; ii++) {
            const float* base = sqe + (k0 + cl) * 136 + i0w + ii * 16 + rw;
            a[ii][0] = __float_as_uint(base[0]);
            a[ii][1] = __float_as_uint(base[8]);
            a[ii][2] = __float_as_uint(base[4 * 136]);
            a[ii][3] = __float_as_uint(base[4 * 136 + 8]);
        }
#pragma unroll
        for (int jj = 0; jj < 4; jj++) {
            const float* bb = ske + (k0 + cl) * 136 + j0w + jj * 8 + rw;
            uint32_t b0 = __float_as_uint(bb[0]);
            uint32_t b1 = __float_as_uint(bb[4 * 136]);
            mma8(c[0][jj], a[0], b0, b1);
            mma8(c[1][jj], a[1], b0, b1);
        }
    }

    // combine: sim = a1*qk + a2*qe + a3*ke (qe/ke tf32-rounded; noise << tf32 MMA noise)
    const float a1 = g_simScale[g], a2 = g_simScale[16 + g], a3 = g_simScale[32 + g];
#pragma unroll
    for (int ii = 0; ii < 2; ii++)
#pragma unroll
        for (int jj = 0; jj < 4; jj++) {
            int ir0 = i0w + ii * 16 + rw;
            int jc = j0w + jj * 8 + 2 * cl;
            float2 q0 = *(const float2*)(sqe + ir0 * 136 + jc);
            float2 k0 = *(const float2*)(ske + ir0 * 136 + jc);
            float2 q1 = *(const float2*)(sqe + (ir0 + 8) * 136 + jc);
            float2 k1 = *(const float2*)(ske + (ir0 + 8) * 136 + jc);
            float* cc = c[ii][jj];
            cc[0] = a1 * cc[0] + a2 * q0.x + a3 * k0.x;
            cc[1] = a1 * cc[1] + a2 * q0.y + a3 * k0.y;
            cc[2] = a1 * cc[2] + a2 * q1.x + a3 * k1.x;
            cc[3] = a1 * cc[3] + a2 * q1.y + a3 * k1.y;
        }
    __syncthreads();

#pragma unroll
    for (int ii = 0; ii < 2; ii++)
#pragma unroll
        for (int jj = 0; jj < 4; jj++) {
            int ir0 = i0w + ii * 16 + rw;
            int jc = j0w + jj * 8 + 2 * cl;
            float* cc = c[ii][jj];
            ssim[ir0 * 133 + jc] = cc[0];
            ssim[ir0 * 133 + jc + 1] = cc[1];
            ssim[(ir0 + 8) * 133 + jc] = cc[2];
            ssim[(ir0 + 8) * 133 + jc + 1] = cc[3];
        }
    __syncthreads();

    // softmax over j: 16 warps x 8 rows
    for (int r = 0; r < 8; r++) {
        int i = w * 8 + r;
        float* row = ssim + i * 133;
        float x0 = row[lane], x1 = row[lane + 32], x2 = row[lane + 64], x3 = row[lane + 96];
        float mx = fmaxf(fmaxf(x0, x1), fmaxf(x2, x3));
#pragma unroll
        for (int o = 16; o > 0; o >>= 1) mx = fmaxf(mx, __shfl_xor_sync(0xffffffffu, mx, o));
        float e0 = __expf(x0 - mx), e1 = __expf(x1 - mx);
        float e2 = __expf(x2 - mx), e3 = __expf(x3 - mx);
        float s = warpSum(e0 + e1 + e2 + e3);
        float inv = 1.f / s;
        row[lane] = e0 * inv; row[lane + 32] = e1 * inv;
        row[lane + 64] = e2 * inv; row[lane + 96] = e3 * inv;
    }
    __syncthreads();

    // am/ame: thread owns (i, 2 channels)
    const int i = t & 127, cg = t >> 7;           // cg in [0,4)
    const float* svp = (cg < 2) ? sva4 : svb4;
    const float* srv = (cg < 2) ? srva : srvb;
    const int off = (cg & 1) * 2;
    float accA[2] = {0.f, 0.f}, accE[2] = {0.f, 0.f};
    for (int j = 0; j < 128; j++) {
        float p = ssim[i * 133 + j];
        int d = i - j + 127;
        float2 v2 = *(const float2*)(svp + 4 * j + off);
        float2 r2 = *(const float2*)(srv + 4 * d + off);
        accA[0] += p * v2.x; accA[1] += p * v2.y;
        accE[0] += p * r2.x; accE[1] += p * r2.y;
    }

    float* dst = g_outraw + (size_t)bh * 32768;
#pragma unroll
    for (int cc = 0; cc < 2; cc++) {
        int ch = cg * 2 + cc;
        int o = g * 16 + 2 * ch;
        dst[o * 128 + i] = accA[cc];
        dst[(o + 1) * 128 + i] = accE[cc];
        float sA = warpSum(accA[cc]);
        float sA2 = warpSum(accA[cc] * accA[cc]);
        float sE = warpSum(accE[cc]);
        float sE2 = warpSum(accE[cc] * accE[cc]);
        if (lane == 0) {
            atomicAdd(&g_outStats[o * 2], sA);
            atomicAdd(&g_outStats[o * 2 + 1], sA2);
            atomicAdd(&g_outStats[(o + 1) * 2], sE);
            atomicAdd(&g_outStats[(o + 1) * 2 + 1], sE2);
        }
    }
}

// ---------------- F: finalize out BN params ----------------
__global__ void kF(const float* __restrict__ gamma_out, const float* __restrict__ beta_out) {
    int o = threadIdx.x;  // 256
    const float N = 16384.f;
    float S = g_outStats[o * 2], S2 = g_outStats[o * 2 + 1];
    float mean = S / N;
    float var = S2 / N - mean * mean;
    float sc = gamma_out[o] * rsqrtf(var + EPSF);
    g_outScale[o] = sc;
    g_outShift[o] = beta_out[o] - mean * sc;
}

// ---------------- G: y = bn(out)[2oc] + bn(out)[2oc+1] ----------------
__global__ __launch_bounds__(256) void kG(float* __restrict__ y) {
    int idx = blockIdx.x * 256 + threadIdx.x;
    int wpos = idx & 127;
    int h = (idx >> 7) & 63;
    int oc = (idx >> 13) & 127;
    int b0 = idx >> 20;
    int bh = b0 * 64 + h;
    int o = oc * 2;
    float v0 = g_outraw[(size_t)bh * 32768 + o * 128 + wpos];
    float v1 = g_outraw[(size_t)bh * 32768 + (o + 1) * 128 + wpos];
    y[idx] = (v0 * g_outScale[o] + g_outShift[o]) + (v1 * g_outScale[o + 1] + g_outShift[o + 1]);
}

// ---------------- launch ----------------
extern "C" void kernel_launch(void* const* d_in, const int* in_sizes, int n_in,
                              void* d_out, int out_size) {
    const float* x  = (const float*)d_in[0];
    const float* W  = (const float*)d_in[1];
    const float* gq = (const float*)d_in[2];
    const float* bq = (const float*)d_in[3];
    const float* re = (const float*)d_in[4];
    const float* gs = (const float*)d_in[5];
    // beta_sim (d_in[6]) cancels inside softmax — unused
    const float* go = (const float*)d_in[7];
    const float* bo = (const float*)d_in[8];
    float* y = (float*)d_out;

    const int SMEM_A = (16896 + 128 * 68) * 4;       // 102400
    const int SMEM_C = (20480 + 17408) * 4;          // 151552
    const int SMEM_E = (23552 + 17408) * 4;          // 163840

    cudaFuncSetAttribute(kA, cudaFuncAttributeMaxDynamicSharedMemorySize, SMEM_A);
    cudaFuncSetAttribute(kC, cudaFuncAttributeMaxDynamicSharedMemorySize, SMEM_C);
    cudaFuncSetAttribute(kE, cudaFuncAttributeMaxDynamicSharedMemorySize, SMEM_E);

    kZero<<<1, 512>>>();
    kA<<<dim3(4, 128), 256, SMEM_A>>>(x, W);
    kBf<<<1, 256>>>(gq, bq);
    kC<<<dim3(16, 128), 512, SMEM_C>>>(re);
    kD<<<1, 64>>>(gs);
    kE<<<dim3(16, 128), 512, SMEM_E>>>(re);
    kF<<<1, 256>>>(go, bo);
    kG<<<8192, 256>>>(y);
}